// round 1
// baseline (speedup 1.0000x reference)
#include <cuda_runtime.h>
#include <cstdint>

// ---- problem constants ----
#define BATCH   1024
#define NNODES  100
#define KD      640      // key dim (5*128)
#define KD4     160      // key dim in float4
#define POOL    128
#define TOPK    4
#define PD      2304     // prompt dim (3*6*128), LENGTH=1
#define PD4     576

// ---- output layout (concatenated flat float32, reference return order) ----
#define OUT_BP  0
#define OUT_RS  (BATCH*TOPK*PD)          // 9437184
#define OUT_SIM (OUT_RS + 1)             // 9437185
#define OUT_US  (OUT_SIM + BATCH*POOL)   // 9568257

// ---- device scratch (no dynamic allocation allowed) ----
__device__ float g_xnorm[BATCH * KD];    // normalized batch keys
__device__ float g_keynorm[POOL * KD];   // normalized pool keys
__device__ int   g_idx[BATCH * TOPK];    // selected pool indices
__device__ float g_partial[128];         // per-block reduce_sim partials
__device__ int   g_usage[POOL];          // usage histogram

// ============================================================
// Kernel 1: mean over nodes + L2 normalize (normalizing the SUM
// is exactly equal to normalizing the mean: scale invariance).
// grid 512, block (160, 2): threadIdx.x = float4 column, .y = row-in-block
// ============================================================
__global__ void k_mean_norm(const float4* __restrict__ x) {
    const int row = blockIdx.x * 2 + threadIdx.y;
    const int c   = threadIdx.x;                       // 0..159
    const float4* xp = x + (size_t)row * (NNODES * KD4) + c;

    float4 a = make_float4(0.f, 0.f, 0.f, 0.f);
    #pragma unroll 4
    for (int n = 0; n < NNODES; n++) {
        float4 v = xp[(size_t)n * KD4];
        a.x += v.x; a.y += v.y; a.z += v.z; a.w += v.w;
    }
    float ss = a.x*a.x + a.y*a.y + a.z*a.z + a.w*a.w;
    #pragma unroll
    for (int o = 16; o; o >>= 1) ss += __shfl_xor_sync(0xffffffffu, ss, o);

    __shared__ float warp_ss[10];
    const int lin = threadIdx.y * 160 + threadIdx.x;
    if ((lin & 31) == 0) warp_ss[lin >> 5] = ss;
    __syncthreads();

    float tot = 0.f;
    const int wbase = threadIdx.y * 5;
    #pragma unroll
    for (int i = 0; i < 5; i++) tot += warp_ss[wbase + i];
    tot = fmaxf(tot, 1e-12f);
    float rs = rsqrtf(tot);
    rs = rs * (1.5f - 0.5f * tot * rs * rs);   // NR refine -> ~2 ulp

    float4* o = reinterpret_cast<float4*>(g_xnorm);
    o[(size_t)row * KD4 + c] = make_float4(a.x*rs, a.y*rs, a.z*rs, a.w*rs);
}

// ============================================================
// Kernel 2: normalize pool keys; zero usage histogram for this replay.
// grid 128, block 160
// ============================================================
__global__ void k_key_norm(const float4* __restrict__ pk) {
    const int p = blockIdx.x;
    const int c = threadIdx.x;
    float4 v = pk[(size_t)p * KD4 + c];
    float ss = v.x*v.x + v.y*v.y + v.z*v.z + v.w*v.w;
    #pragma unroll
    for (int o = 16; o; o >>= 1) ss += __shfl_xor_sync(0xffffffffu, ss, o);

    __shared__ float warp_ss[5];
    if ((threadIdx.x & 31) == 0) warp_ss[threadIdx.x >> 5] = ss;
    __syncthreads();
    float tot = 0.f;
    #pragma unroll
    for (int i = 0; i < 5; i++) tot += warp_ss[i];
    tot = fmaxf(tot, 1e-12f);
    float rs = rsqrtf(tot);
    rs = rs * (1.5f - 0.5f * tot * rs * rs);

    float4* o = reinterpret_cast<float4*>(g_keynorm);
    o[(size_t)p * KD4 + c] = make_float4(v.x*rs, v.y*rs, v.z*rs, v.w*rs);

    if (threadIdx.x == 0) g_usage[p] = 0;
}

// ============================================================
// Kernel 3: similarity (8 rows x 128 pools per block) + top-4 + partials.
// Block: 256 threads = 8 warps. Each warp owns 16 pools.
// Within a warp: lane = (q<<3)|r -> row r (0..7), dim-quarter q (0..3).
// All lanes of a q-group read the SAME key word (L1 broadcast, 1 line).
// xs padded to 644 floats/row: bank = (4r+4j) mod 32 -> conflict-free.
// ============================================================
__global__ void k_sim_topk(float* __restrict__ out) {
    __shared__ float xs[8 * 644];
    __shared__ float sims[8 * 132];
    __shared__ float wsum[8];

    const int rb = blockIdx.x * 8;
    const int t  = threadIdx.x;

    for (int l = t; l < 8 * KD; l += 256) {
        int r = l / KD, d = l - r * KD;
        xs[r * 644 + d] = g_xnorm[(size_t)(rb + r) * KD + d];
    }
    __syncthreads();

    const int w    = t >> 5;
    const int lane = t & 31;
    const int q    = lane >> 3;   // dim quarter
    const int r    = lane & 7;    // row
    const float4* xs4 = reinterpret_cast<const float4*>(xs);
    const float4* kn4 = reinterpret_cast<const float4*>(g_keynorm);

    for (int pi = 0; pi < 16; pi++) {
        const int p = w * 16 + pi;
        const float4* kp = kn4 + (size_t)p * KD4 + q * 40;
        const float4* xp = xs4 + r * 161 + q * 40;
        float a0 = 0.f, a1 = 0.f;
        #pragma unroll 10
        for (int j = 0; j < 40; j += 2) {
            float4 k0 = kp[j],   x0 = xp[j];
            a0 = fmaf(k0.x, x0.x, a0); a0 = fmaf(k0.y, x0.y, a0);
            a0 = fmaf(k0.z, x0.z, a0); a0 = fmaf(k0.w, x0.w, a0);
            float4 k1 = kp[j+1], x1 = xp[j+1];
            a1 = fmaf(k1.x, x1.x, a1); a1 = fmaf(k1.y, x1.y, a1);
            a1 = fmaf(k1.z, x1.z, a1); a1 = fmaf(k1.w, x1.w, a1);
        }
        float v = a0 + a1;
        v += __shfl_xor_sync(0xffffffffu, v, 8);
        v += __shfl_xor_sync(0xffffffffu, v, 16);
        if (lane < 8) sims[lane * 132 + p] = v;
    }
    __syncthreads();

    // ---- top-4 per row: warp w handles row w. Composite key:
    // monotone float->uint in high 32 bits, (127-pool) in low bits
    // -> max composite = max value, ties broken by smallest pool index
    // (matches jax.lax.top_k stable ordering).
    {
        const int rw = w;
        float vals[4];
        #pragma unroll
        for (int s = 0; s < 4; s++) vals[s] = sims[rw * 132 + lane + 32 * s];

        float vsum = 0.f;
        #pragma unroll
        for (int k = 0; k < TOPK; k++) {
            unsigned long long best = 0ull;
            #pragma unroll
            for (int s = 0; s < 4; s++) {
                unsigned u = __float_as_uint(vals[s]);
                u = (u & 0x80000000u) ? ~u : (u | 0x80000000u);
                unsigned pidx = lane + 32u * s;
                unsigned long long comp =
                    ((unsigned long long)u << 32) | (127u - pidx);
                if (comp > best) best = comp;
            }
            #pragma unroll
            for (int o = 16; o; o >>= 1) {
                unsigned long long other = __shfl_xor_sync(0xffffffffu, best, o);
                if (other > best) best = other;
            }
            unsigned pool = 127u - (unsigned)(best & 0xffffffffu);
            unsigned u = (unsigned)(best >> 32);
            unsigned orig = (u & 0x80000000u) ? (u ^ 0x80000000u) : ~u;
            vsum += __uint_as_float(orig);

            if (lane == (int)(pool & 31u)) vals[pool >> 5] = -1e30f;
            if (lane == 0) {
                g_idx[(rb + rw) * TOPK + k] = (int)pool;
                atomicAdd(&g_usage[pool], 1);
            }
        }
        if (lane == 0) wsum[rw] = vsum;
    }
    __syncthreads();

    if (t == 0) {
        float s = 0.f;
        #pragma unroll
        for (int i = 0; i < 8; i++) s += wsum[i];   // fixed order: deterministic
        g_partial[blockIdx.x] = s;
    }

    // similarity output (coalesced)
    for (int l = t; l < 8 * POOL; l += 256) {
        int r2 = l >> 7, p2 = l & 127;
        out[OUT_SIM + (size_t)(rb + r2) * POOL + p2] = sims[r2 * 132 + p2];
    }
}

// ============================================================
// Kernel 4: gather selected prompts. grid (4, 1024), block 256.
// Pool is 1.18 MB -> L2 resident; write-bound (37.7 MB).
// ============================================================
__global__ void k_gather(const float4* __restrict__ prompt, float4* __restrict__ outbp) {
    const int b = blockIdx.y, k = blockIdx.x;
    const int idx = g_idx[b * TOPK + k];
    const float4* src = prompt + (size_t)idx * PD4;
    float4* dst = outbp + ((size_t)b * TOPK + k) * PD4;
    for (int i = threadIdx.x; i < PD4; i += 256) dst[i] = src[i];
}

// ============================================================
// Kernel 5: deterministic final reduce of reduce_sim + usage counts.
// ============================================================
__global__ void k_final(float* __restrict__ out) {
    __shared__ float s[128];
    const int t = threadIdx.x;
    s[t] = g_partial[t];
    __syncthreads();
    #pragma unroll
    for (int o = 64; o; o >>= 1) {
        if (t < o) s[t] += s[t + o];
        __syncthreads();
    }
    if (t == 0) out[OUT_RS] = s[0] * (1.0f / (float)BATCH);
    out[OUT_US + t] = (float)g_usage[t];
}

// ============================================================
extern "C" void kernel_launch(void* const* d_in, const int* in_sizes, int n_in,
                              void* d_out, int out_size) {
    const float* x      = (const float*)d_in[0];  // [1024, 100, 640]
    const float* prompt = (const float*)d_in[1];  // [128, 1, 2304]
    const float* pkey   = (const float*)d_in[2];  // [128, 640]
    float* out = (float*)d_out;

    k_mean_norm<<<512, dim3(160, 2)>>>(reinterpret_cast<const float4*>(x));
    k_key_norm<<<128, 160>>>(reinterpret_cast<const float4*>(pkey));
    k_sim_topk<<<128, 256>>>(out);
    k_gather<<<dim3(4, 1024), 256>>>(reinterpret_cast<const float4*>(prompt),
                                     reinterpret_cast<float4*>(out));
    k_final<<<1, 128>>>(out);
}

// round 2
// speedup vs baseline: 1.0323x; 1.0323x over previous
#include <cuda_runtime.h>
#include <cstdint>

// ---- problem constants ----
#define BATCH   1024
#define NNODES  100
#define KD      640      // key dim (5*128)
#define KD4     160      // key dim in float4
#define POOL    128
#define TOPK    4
#define PD      2304     // prompt dim (3*6*128), LENGTH=1
#define PD4     576

// ---- output layout (concatenated flat float32, reference return order) ----
#define OUT_BP  0
#define OUT_RS  (BATCH*TOPK*PD)          // 9437184
#define OUT_SIM (OUT_RS + 1)             // 9437185
#define OUT_US  (OUT_SIM + BATCH*POOL)   // 9568257

// ---- device scratch (no dynamic allocation allowed) ----
__device__ float g_xnorm[BATCH * KD];    // normalized batch keys
__device__ float g_keynorm[POOL * KD];   // normalized pool keys
__device__ int   g_idx[BATCH * TOPK];    // selected pool indices
__device__ float g_partial[128];         // per-block reduce_sim partials
__device__ int   g_usage[POOL];          // usage histogram

// ============================================================
// Kernel 1 (fused): blocks 0..1023  -> per-row mean + L2 normalize
//                   blocks 1024..1151 -> pool-key normalize + usage zero
// Block (160, 2) = 320 threads. Mean path: threadIdx.y selects node half
// (50 nodes each, unroll 10 -> ~10 independent LDG.128 in flight/thread).
// Normalizing the SUM == normalizing the mean (scale invariance).
// ============================================================
__global__ void k1_norm(const float4* __restrict__ x, const float4* __restrict__ pk) {
    const int c   = threadIdx.x;                        // 0..159
    const int tid = threadIdx.y * 160 + threadIdx.x;    // 0..319
    const int lane = tid & 31, warp = tid >> 5;         // 10 warps

    __shared__ float4 part[160];
    __shared__ float  wss[10];

    if (blockIdx.x < BATCH) {
        // ---------------- row mean + normalize ----------------
        const int row = blockIdx.x;
        const float4* xp = x + (size_t)row * (NNODES * KD4)
                             + (size_t)threadIdx.y * 50 * KD4 + c;
        float4 a = make_float4(0.f, 0.f, 0.f, 0.f);
        #pragma unroll 10
        for (int n = 0; n < 50; n++) {
            float4 v = xp[(size_t)n * KD4];
            a.x += v.x; a.y += v.y; a.z += v.z; a.w += v.w;
        }
        if (threadIdx.y == 1) part[c] = a;
        __syncthreads();
        float ss = 0.f;
        if (threadIdx.y == 0) {
            float4 b = part[c];
            a.x += b.x; a.y += b.y; a.z += b.z; a.w += b.w;
            ss = a.x*a.x + a.y*a.y + a.z*a.z + a.w*a.w;
        }
        #pragma unroll
        for (int o = 16; o; o >>= 1) ss += __shfl_xor_sync(0xffffffffu, ss, o);
        if (lane == 0) wss[warp] = ss;
        __syncthreads();
        if (threadIdx.y == 0) {
            float tot = wss[0] + wss[1] + wss[2] + wss[3] + wss[4];
            tot = fmaxf(tot, 1e-12f);
            float rs = rsqrtf(tot);
            rs = rs * (1.5f - 0.5f * tot * rs * rs);   // NR refine
            float4* o4 = reinterpret_cast<float4*>(g_xnorm);
            o4[(size_t)row * KD4 + c] = make_float4(a.x*rs, a.y*rs, a.z*rs, a.w*rs);
        }
    } else {
        // ---------------- pool key normalize ----------------
        const int p = blockIdx.x - BATCH;
        float4 v = make_float4(0.f, 0.f, 0.f, 0.f);
        float ss = 0.f;
        if (tid < 160) {
            v = pk[(size_t)p * KD4 + tid];
            ss = v.x*v.x + v.y*v.y + v.z*v.z + v.w*v.w;
        }
        #pragma unroll
        for (int o = 16; o; o >>= 1) ss += __shfl_xor_sync(0xffffffffu, ss, o);
        if (lane == 0) wss[warp] = ss;
        __syncthreads();
        float tot = wss[0] + wss[1] + wss[2] + wss[3] + wss[4];
        tot = fmaxf(tot, 1e-12f);
        float rs = rsqrtf(tot);
        rs = rs * (1.5f - 0.5f * tot * rs * rs);
        if (tid < 160) {
            float4* o4 = reinterpret_cast<float4*>(g_keynorm);
            o4[(size_t)p * KD4 + tid] = make_float4(v.x*rs, v.y*rs, v.z*rs, v.w*rs);
        }
        if (tid == 160) g_usage[p] = 0;
    }
}

// ============================================================
// Kernel 2: similarity (8 rows x 128 pools per block) + top-4 + partials.
// Block: 256 threads = 8 warps. Each warp owns 16 pools.
// lane = (q<<3)|r -> row r (0..7), dim-quarter q (0..3); all lanes of a
// q-group read the SAME key word (L1 broadcast). xs padded 644/row.
// ============================================================
__global__ void k_sim_topk(float* __restrict__ out) {
    __shared__ float xs[8 * 644];
    __shared__ float sims[8 * 132];
    __shared__ float wsum[8];

    const int rb = blockIdx.x * 8;
    const int t  = threadIdx.x;

    for (int l = t; l < 8 * KD; l += 256) {
        int r = l / KD, d = l - r * KD;
        xs[r * 644 + d] = g_xnorm[(size_t)(rb + r) * KD + d];
    }
    __syncthreads();

    const int w    = t >> 5;
    const int lane = t & 31;
    const int q    = lane >> 3;
    const int r    = lane & 7;
    const float4* xs4 = reinterpret_cast<const float4*>(xs);
    const float4* kn4 = reinterpret_cast<const float4*>(g_keynorm);

    for (int pi = 0; pi < 16; pi++) {
        const int p = w * 16 + pi;
        const float4* kp = kn4 + (size_t)p * KD4 + q * 40;
        const float4* xp = xs4 + r * 161 + q * 40;
        float a0 = 0.f, a1 = 0.f;
        #pragma unroll 10
        for (int j = 0; j < 40; j += 2) {
            float4 k0 = kp[j],   x0 = xp[j];
            a0 = fmaf(k0.x, x0.x, a0); a0 = fmaf(k0.y, x0.y, a0);
            a0 = fmaf(k0.z, x0.z, a0); a0 = fmaf(k0.w, x0.w, a0);
            float4 k1 = kp[j+1], x1 = xp[j+1];
            a1 = fmaf(k1.x, x1.x, a1); a1 = fmaf(k1.y, x1.y, a1);
            a1 = fmaf(k1.z, x1.z, a1); a1 = fmaf(k1.w, x1.w, a1);
        }
        float v = a0 + a1;
        v += __shfl_xor_sync(0xffffffffu, v, 8);
        v += __shfl_xor_sync(0xffffffffu, v, 16);
        if (lane < 8) sims[lane * 132 + p] = v;
    }
    __syncthreads();

    // top-4 per row (warp w -> row w); composite key = monotone float bits
    // in high word, (127-pool) low -> max picks max value, smallest index
    // on ties (matches jax.lax.top_k).
    {
        const int rw = w;
        float vals[4];
        #pragma unroll
        for (int s = 0; s < 4; s++) vals[s] = sims[rw * 132 + lane + 32 * s];

        float vsum = 0.f;
        #pragma unroll
        for (int k = 0; k < TOPK; k++) {
            unsigned long long best = 0ull;
            #pragma unroll
            for (int s = 0; s < 4; s++) {
                unsigned u = __float_as_uint(vals[s]);
                u = (u & 0x80000000u) ? ~u : (u | 0x80000000u);
                unsigned pidx = lane + 32u * s;
                unsigned long long comp =
                    ((unsigned long long)u << 32) | (127u - pidx);
                if (comp > best) best = comp;
            }
            #pragma unroll
            for (int o = 16; o; o >>= 1) {
                unsigned long long other = __shfl_xor_sync(0xffffffffu, best, o);
                if (other > best) best = other;
            }
            unsigned pool = 127u - (unsigned)(best & 0xffffffffu);
            unsigned u = (unsigned)(best >> 32);
            unsigned orig = (u & 0x80000000u) ? (u ^ 0x80000000u) : ~u;
            vsum += __uint_as_float(orig);

            if (lane == (int)(pool & 31u)) vals[pool >> 5] = -1e30f;
            if (lane == 0) {
                g_idx[(rb + rw) * TOPK + k] = (int)pool;
                atomicAdd(&g_usage[pool], 1);
            }
        }
        if (lane == 0) wsum[rw] = vsum;
    }
    __syncthreads();

    if (t == 0) {
        float s = 0.f;
        #pragma unroll
        for (int i = 0; i < 8; i++) s += wsum[i];   // fixed order -> deterministic
        g_partial[blockIdx.x] = s;
    }

    for (int l = t; l < 8 * POOL; l += 256) {
        int r2 = l >> 7, p2 = l & 127;
        out[OUT_SIM + (size_t)(rb + r2) * POOL + p2] = sims[r2 * 132 + p2];
    }
}

// ============================================================
// Kernel 3 (fused): blocks 0..1023 -> gather (batch-load 9 float4 into
// regs, then batch-store: MLP 9 instead of load->store dependency chain).
// Block 1024 -> final reduce_sim + usage output.
// ============================================================
__global__ void k3_gather_final(const float4* __restrict__ prompt,
                                float* __restrict__ out) {
    if (blockIdx.x < BATCH) {
        const int b = blockIdx.x;
        const int t = threadIdx.x;   // 256 threads
        int idxs[TOPK];
        #pragma unroll
        for (int k = 0; k < TOPK; k++) idxs[k] = g_idx[b * TOPK + k];

        float4 vals[9];
        #pragma unroll
        for (int j = 0; j < 9; j++) {
            int pos = t + 256 * j;          // 0..2303 over [K=4][PD4=576]
            int k   = pos / PD4;
            int off = pos - k * PD4;
            vals[j] = prompt[(size_t)idxs[k] * PD4 + off];
        }
        float4* dst = reinterpret_cast<float4*>(out) + (size_t)b * (TOPK * PD4);
        #pragma unroll
        for (int j = 0; j < 9; j++) dst[t + 256 * j] = vals[j];
    } else {
        __shared__ float s[128];
        const int t = threadIdx.x;
        if (t < 128) s[t] = g_partial[t];
        __syncthreads();
        #pragma unroll
        for (int o = 64; o; o >>= 1) {
            if (t < o) s[t] += s[t + o];
            __syncthreads();
        }
        if (t == 0) out[OUT_RS] = s[0] * (1.0f / (float)BATCH);
        if (t < 128) out[OUT_US + t] = (float)g_usage[t];
    }
}

// ============================================================
extern "C" void kernel_launch(void* const* d_in, const int* in_sizes, int n_in,
                              void* d_out, int out_size) {
    const float* x      = (const float*)d_in[0];  // [1024, 100, 640]
    const float* prompt = (const float*)d_in[1];  // [128, 1, 2304]
    const float* pkey   = (const float*)d_in[2];  // [128, 640]
    float* out = (float*)d_out;

    k1_norm<<<BATCH + POOL, dim3(160, 2)>>>(
        reinterpret_cast<const float4*>(x),
        reinterpret_cast<const float4*>(pkey));
    k_sim_topk<<<128, 256>>>(out);
    k3_gather_final<<<BATCH + 1, 256>>>(
        reinterpret_cast<const float4*>(prompt), out);
}

// round 3
// speedup vs baseline: 1.4724x; 1.4263x over previous
#include <cuda_runtime.h>
#include <cstdint>

// ---- problem constants ----
#define BATCH   1024
#define NNODES  100
#define KD      640      // key dim (5*128)
#define KD4     160      // key dim in float4
#define POOL    128
#define TOPK    4
#define PD      2304     // prompt dim
#define PD4     576

// ---- output layout (flat float32, reference return order) ----
#define OUT_RS  (BATCH*TOPK*PD)          // 9437184
#define OUT_SIM (OUT_RS + 1)             // 9437185
#define OUT_US  (OUT_SIM + BATCH*POOL)   // 9568257

// ---- device scratch ----
__device__ float g_xnorm[BATCH * KD];
__device__ float g_keynorm[POOL * KD];
__device__ int   g_idx[BATCH * TOPK];
__device__ float g_partial[128];
__device__ int   g_counter;

// ============================================================
// Kernel 1: blocks 0..1023 -> per-row mean + L2 normalize
//           blocks 1024..1151 -> pool-key normalize (+ counter reset)
// ============================================================
__global__ __launch_bounds__(320, 4) void k1_norm(const float4* __restrict__ x,
                                                  const float4* __restrict__ pk) {
    const int c   = threadIdx.x;                        // 0..159
    const int tid = threadIdx.y * 160 + threadIdx.x;    // 0..319
    const int lane = tid & 31, warp = tid >> 5;

    __shared__ float4 part[160];
    __shared__ float  wss[10];

    if (blockIdx.x < BATCH) {
        const int row = blockIdx.x;
        const float4* xp = x + (size_t)row * (NNODES * KD4)
                             + (size_t)threadIdx.y * 50 * KD4 + c;
        float4 a = make_float4(0.f, 0.f, 0.f, 0.f);
        #pragma unroll 10
        for (int n = 0; n < 50; n++) {
            float4 v = xp[(size_t)n * KD4];
            a.x += v.x; a.y += v.y; a.z += v.z; a.w += v.w;
        }
        if (threadIdx.y == 1) part[c] = a;
        __syncthreads();
        float ss = 0.f;
        if (threadIdx.y == 0) {
            float4 b = part[c];
            a.x += b.x; a.y += b.y; a.z += b.z; a.w += b.w;
            ss = a.x*a.x + a.y*a.y + a.z*a.z + a.w*a.w;
        }
        #pragma unroll
        for (int o = 16; o; o >>= 1) ss += __shfl_xor_sync(0xffffffffu, ss, o);
        if (lane == 0) wss[warp] = ss;
        __syncthreads();
        if (threadIdx.y == 0) {
            float tot = wss[0] + wss[1] + wss[2] + wss[3] + wss[4];
            tot = fmaxf(tot, 1e-12f);
            float rs = rsqrtf(tot);
            rs = rs * (1.5f - 0.5f * tot * rs * rs);   // NR refine
            float4* o4 = reinterpret_cast<float4*>(g_xnorm);
            o4[(size_t)row * KD4 + c] = make_float4(a.x*rs, a.y*rs, a.z*rs, a.w*rs);
        }
    } else {
        const int p = blockIdx.x - BATCH;
        float4 v = make_float4(0.f, 0.f, 0.f, 0.f);
        float ss = 0.f;
        if (tid < 160) {
            v = pk[(size_t)p * KD4 + tid];
            ss = v.x*v.x + v.y*v.y + v.z*v.z + v.w*v.w;
        }
        #pragma unroll
        for (int o = 16; o; o >>= 1) ss += __shfl_xor_sync(0xffffffffu, ss, o);
        if (lane == 0) wss[warp] = ss;
        __syncthreads();
        float tot = wss[0] + wss[1] + wss[2] + wss[3] + wss[4];
        tot = fmaxf(tot, 1e-12f);
        float rs = rsqrtf(tot);
        rs = rs * (1.5f - 0.5f * tot * rs * rs);
        if (tid < 160) {
            float4* o4 = reinterpret_cast<float4*>(g_keynorm);
            o4[(size_t)p * KD4 + tid] = make_float4(v.x*rs, v.y*rs, v.z*rs, v.w*rs);
        }
        if (tid == 160 && p == 0) g_counter = 0;   // per-call reset
    }
}

// ============================================================
// Kernel 2 (fused): GEMM (8 rows x 128 pools) via smem-staged,
// register-tiled chunks; top-4; sim write; in-block gather;
// last-block final (reduce_sim + usage histogram from g_idx).
// 128 blocks x 512 threads.
// ============================================================
__global__ __launch_bounds__(512) void k2_fused(const float4* __restrict__ prompt,
                                                float* __restrict__ out) {
    __shared__ float kt[POOL][68];     // key chunk, padded rows (34.8KB)
    __shared__ float xsc[8][68];       // x chunk
    __shared__ float sims[8][132];
    __shared__ int   sidx[32];
    __shared__ float wsum[8];
    __shared__ int   histo[POOL];
    __shared__ int   lastf;

    const int t = threadIdx.x;
    const int w = t >> 5, lane = t & 31;
    const int q = lane >> 3, r = lane & 7;   // dim-quarter-of-16, row
    const int rb = blockIdx.x * 8;
    const int pbase = w * 8;                 // 16 warps x 8 pools = 128

    const float4* kg = reinterpret_cast<const float4*>(g_keynorm);
    const float4* xg = reinterpret_cast<const float4*>(g_xnorm);

    // staging descriptors (fixed across chunks)
    int kp[4], kf[4];
    #pragma unroll
    for (int i = 0; i < 4; i++) { int fi = t + 512*i; kp[i] = fi >> 4; kf[i] = fi & 15; }
    const int xr = t >> 4, xf = t & 15;

    // prefetch + store chunk 0
    float4 kv[4]; float4 xv = make_float4(0.f,0.f,0.f,0.f);
    #pragma unroll
    for (int i = 0; i < 4; i++) kv[i] = kg[kp[i]*KD4 + kf[i]];
    if (t < 128) xv = xg[(size_t)(rb + xr)*KD4 + xf];
    #pragma unroll
    for (int i = 0; i < 4; i++) *reinterpret_cast<float4*>(&kt[kp[i]][kf[i]*4]) = kv[i];
    if (t < 128) *reinterpret_cast<float4*>(&xsc[xr][xf*4]) = xv;

    float acc[8];
    #pragma unroll
    for (int u = 0; u < 8; u++) acc[u] = 0.f;

    for (int c = 0; c < 10; c++) {
        __syncthreads();                       // chunk c staged
        if (c < 9) {                           // prefetch c+1 (hidden under FFMA)
            #pragma unroll
            for (int i = 0; i < 4; i++) kv[i] = kg[kp[i]*KD4 + (c+1)*16 + kf[i]];
            if (t < 128) xv = xg[(size_t)(rb + xr)*KD4 + (c+1)*16 + xf];
        }
        #pragma unroll
        for (int j = 0; j < 4; j++) {
            const int d = j*16 + q*4;
            float4 x4 = *reinterpret_cast<const float4*>(&xsc[r][d]);
            #pragma unroll
            for (int u = 0; u < 8; u++) {
                float4 k4 = *reinterpret_cast<const float4*>(&kt[pbase + u][d]);
                acc[u] = fmaf(x4.x, k4.x, acc[u]);
                acc[u] = fmaf(x4.y, k4.y, acc[u]);
                acc[u] = fmaf(x4.z, k4.z, acc[u]);
                acc[u] = fmaf(x4.w, k4.w, acc[u]);
            }
        }
        __syncthreads();                       // compute done, safe to overwrite
        if (c < 9) {
            #pragma unroll
            for (int i = 0; i < 4; i++) *reinterpret_cast<float4*>(&kt[kp[i]][kf[i]*4]) = kv[i];
            if (t < 128) *reinterpret_cast<float4*>(&xsc[xr][xf*4]) = xv;
        }
    }

    // reduce over q lanes (bits 3,4)
    #pragma unroll
    for (int u = 0; u < 8; u++) {
        acc[u] += __shfl_xor_sync(0xffffffffu, acc[u], 8);
        acc[u] += __shfl_xor_sync(0xffffffffu, acc[u], 16);
    }
    if (q == 0) {
        #pragma unroll
        for (int u = 0; u < 8; u++) sims[r][pbase + u] = acc[u];
    }
    __syncthreads();

    // similarity output (coalesced)
    for (int l = t; l < 8 * POOL; l += 512) {
        int rr = l >> 7, pp = l & 127;
        out[OUT_SIM + (size_t)(rb + rr) * POOL + pp] = sims[rr][pp];
    }

    // top-4: warps 0..7 -> rows 0..7 (monotone-bits composite, smallest-index ties)
    if (w < 8) {
        float vals[4];
        #pragma unroll
        for (int s = 0; s < 4; s++) vals[s] = sims[w][lane + 32*s];
        float vsum = 0.f;
        #pragma unroll
        for (int k = 0; k < TOPK; k++) {
            unsigned long long best = 0ull;
            #pragma unroll
            for (int s = 0; s < 4; s++) {
                unsigned u = __float_as_uint(vals[s]);
                u = (u & 0x80000000u) ? ~u : (u | 0x80000000u);
                unsigned long long comp =
                    ((unsigned long long)u << 32) | (127u - (lane + 32u*s));
                if (comp > best) best = comp;
            }
            #pragma unroll
            for (int o = 16; o; o >>= 1) {
                unsigned long long other = __shfl_xor_sync(0xffffffffu, best, o);
                if (other > best) best = other;
            }
            unsigned pool = 127u - (unsigned)(best & 0xffffffffu);
            unsigned ub = (unsigned)(best >> 32);
            unsigned orig = (ub & 0x80000000u) ? (ub ^ 0x80000000u) : ~ub;
            vsum += __uint_as_float(orig);
            if (lane == (int)(pool & 31u)) vals[pool >> 5] = -1e30f;
            if (lane == 0) {
                g_idx[(rb + w) * TOPK + k] = (int)pool;
                sidx[w * 4 + k] = (int)pool;
            }
        }
        if (lane == 0) wsum[w] = vsum;
    }
    __syncthreads();

    // in-block gather: 32 segments x 576 float4 = 18432 float4, 36/thread,
    // batched 6 deep for MLP.
    float4* outbp = reinterpret_cast<float4*>(out);
    for (int s0 = 0; s0 < 36; s0 += 6) {
        float4 v[6]; int di[6];
        #pragma unroll
        for (int k = 0; k < 6; k++) {
            int i   = t + 512 * (s0 + k);
            int seg = i / 576;
            int off = i - seg * 576;
            v[k]  = prompt[(size_t)sidx[seg] * PD4 + off];
            di[k] = (rb * 4 + seg) * PD4 + off;
        }
        #pragma unroll
        for (int k = 0; k < 6; k++) outbp[di[k]] = v[k];
    }

    // per-block partial (fixed order -> deterministic)
    if (t == 0) {
        float s = 0.f;
        #pragma unroll
        for (int i = 0; i < 8; i++) s += wsum[i];
        g_partial[blockIdx.x] = s;
    }
    __syncthreads();
    __threadfence();
    if (t == 0) lastf = (atomicAdd(&g_counter, 1) == 127);
    __syncthreads();

    if (lastf) {
        __threadfence();   // acquire side
        float* red = &sims[0][0];
        if (t < 128) { red[t] = g_partial[t]; histo[t] = 0; }
        __syncthreads();
        #pragma unroll
        for (int o = 64; o; o >>= 1) {
            if (t < o) red[t] += red[t + o];
            __syncthreads();
        }
        if (t == 0) out[OUT_RS] = red[0] * (1.0f / (float)BATCH);
        #pragma unroll
        for (int i = 0; i < 8; i++) atomicAdd(&histo[g_idx[t + 512 * i]], 1);
        __syncthreads();
        if (t < 128) out[OUT_US + t] = (float)histo[t];
    }
}

// ============================================================
extern "C" void kernel_launch(void* const* d_in, const int* in_sizes, int n_in,
                              void* d_out, int out_size) {
    const float* x      = (const float*)d_in[0];  // [1024, 100, 640]
    const float* prompt = (const float*)d_in[1];  // [128, 1, 2304]
    const float* pkey   = (const float*)d_in[2];  // [128, 640]
    float* out = (float*)d_out;

    k1_norm<<<BATCH + POOL, dim3(160, 2)>>>(
        reinterpret_cast<const float4*>(x),
        reinterpret_cast<const float4*>(pkey));
    k2_fused<<<128, 512>>>(reinterpret_cast<const float4*>(prompt), out);
}

// round 4
// speedup vs baseline: 1.4730x; 1.0004x over previous
#include <cuda_runtime.h>
#include <cstdint>

// ---- problem constants ----
#define BATCH   1024
#define NNODES  100
#define KD      640      // key dim (5*128)
#define KD4     160      // key dim in float4
#define POOL    128
#define TOPK    4
#define PD      2304     // prompt dim
#define PD4     576

// ---- output layout (flat float32, reference return order) ----
#define OUT_RS  (BATCH*TOPK*PD)          // 9437184
#define OUT_SIM (OUT_RS + 1)             // 9437185
#define OUT_US  (OUT_SIM + BATCH*POOL)   // 9568257

// ---- device scratch ----
__device__ float g_xnorm[BATCH * KD];
__device__ float g_keynorm[POOL * KD];
__device__ int   g_idx[BATCH * TOPK];
__device__ float g_partial[128];

// ============================================================
// Kernel 1: blocks 0..1023 -> per-row mean + L2 normalize
//           blocks 1024..1151 -> pool-key normalize
// Normalizing the SUM == normalizing the mean (scale invariance).
// ============================================================
__global__ __launch_bounds__(320, 4) void k1_norm(const float4* __restrict__ x,
                                                  const float4* __restrict__ pk) {
    const int c   = threadIdx.x;                        // 0..159
    const int tid = threadIdx.y * 160 + threadIdx.x;    // 0..319
    const int lane = tid & 31, warp = tid >> 5;

    __shared__ float4 part[160];
    __shared__ float  wss[10];

    if (blockIdx.x < BATCH) {
        const int row = blockIdx.x;
        const float4* xp = x + (size_t)row * (NNODES * KD4)
                             + (size_t)threadIdx.y * 50 * KD4 + c;
        float4 a = make_float4(0.f, 0.f, 0.f, 0.f);
        #pragma unroll 10
        for (int n = 0; n < 50; n++) {
            float4 v = xp[(size_t)n * KD4];
            a.x += v.x; a.y += v.y; a.z += v.z; a.w += v.w;
        }
        if (threadIdx.y == 1) part[c] = a;
        __syncthreads();
        float ss = 0.f;
        if (threadIdx.y == 0) {
            float4 b = part[c];
            a.x += b.x; a.y += b.y; a.z += b.z; a.w += b.w;
            ss = a.x*a.x + a.y*a.y + a.z*a.z + a.w*a.w;
        }
        #pragma unroll
        for (int o = 16; o; o >>= 1) ss += __shfl_xor_sync(0xffffffffu, ss, o);
        if (lane == 0) wss[warp] = ss;
        __syncthreads();
        if (threadIdx.y == 0) {
            float tot = wss[0] + wss[1] + wss[2] + wss[3] + wss[4];
            tot = fmaxf(tot, 1e-12f);
            float rs = rsqrtf(tot);
            rs = rs * (1.5f - 0.5f * tot * rs * rs);   // NR refine
            float4* o4 = reinterpret_cast<float4*>(g_xnorm);
            o4[(size_t)row * KD4 + c] = make_float4(a.x*rs, a.y*rs, a.z*rs, a.w*rs);
        }
    } else {
        const int p = blockIdx.x - BATCH;
        float4 v = make_float4(0.f, 0.f, 0.f, 0.f);
        float ss = 0.f;
        if (tid < 160) {
            v = pk[(size_t)p * KD4 + tid];
            ss = v.x*v.x + v.y*v.y + v.z*v.z + v.w*v.w;
        }
        #pragma unroll
        for (int o = 16; o; o >>= 1) ss += __shfl_xor_sync(0xffffffffu, ss, o);
        if (lane == 0) wss[warp] = ss;
        __syncthreads();
        float tot = wss[0] + wss[1] + wss[2] + wss[3] + wss[4];
        tot = fmaxf(tot, 1e-12f);
        float rs = rsqrtf(tot);
        rs = rs * (1.5f - 0.5f * tot * rs * rs);
        if (tid < 160) {
            float4* o4 = reinterpret_cast<float4*>(g_keynorm);
            o4[(size_t)p * KD4 + tid] = make_float4(v.x*rs, v.y*rs, v.z*rs, v.w*rs);
        }
    }
}

// ============================================================
// Kernel B: sim GEMM (8 rows x 128 pools per block) + top-4.
// 128 blocks x 512 threads; smem-staged chunks, register tile of
// 8 pools/lane, double-buffered via register prefetch.
// ============================================================
__global__ __launch_bounds__(512) void kB_sim_topk(float* __restrict__ out) {
    __shared__ float kt[POOL][68];     // key chunk, padded rows
    __shared__ float xsc[8][68];       // x chunk
    __shared__ float sims[8][132];
    __shared__ float wsum[8];

    const int t = threadIdx.x;
    const int w = t >> 5, lane = t & 31;
    const int q = lane >> 3, r = lane & 7;   // dim-quarter, row
    const int rb = blockIdx.x * 8;
    const int pbase = w * 8;                 // 16 warps x 8 pools

    const float4* kg = reinterpret_cast<const float4*>(g_keynorm);
    const float4* xg = reinterpret_cast<const float4*>(g_xnorm);

    int kp[4], kf[4];
    #pragma unroll
    for (int i = 0; i < 4; i++) { int fi = t + 512*i; kp[i] = fi >> 4; kf[i] = fi & 15; }
    const int xr = t >> 4, xf = t & 15;

    float4 kv[4]; float4 xv = make_float4(0.f,0.f,0.f,0.f);
    #pragma unroll
    for (int i = 0; i < 4; i++) kv[i] = kg[kp[i]*KD4 + kf[i]];
    if (t < 128) xv = xg[(size_t)(rb + xr)*KD4 + xf];
    #pragma unroll
    for (int i = 0; i < 4; i++) *reinterpret_cast<float4*>(&kt[kp[i]][kf[i]*4]) = kv[i];
    if (t < 128) *reinterpret_cast<float4*>(&xsc[xr][xf*4]) = xv;

    float acc[8];
    #pragma unroll
    for (int u = 0; u < 8; u++) acc[u] = 0.f;

    for (int c = 0; c < 10; c++) {
        __syncthreads();
        if (c < 9) {
            #pragma unroll
            for (int i = 0; i < 4; i++) kv[i] = kg[kp[i]*KD4 + (c+1)*16 + kf[i]];
            if (t < 128) xv = xg[(size_t)(rb + xr)*KD4 + (c+1)*16 + xf];
        }
        #pragma unroll
        for (int j = 0; j < 4; j++) {
            const int d = j*16 + q*4;
            float4 x4 = *reinterpret_cast<const float4*>(&xsc[r][d]);
            #pragma unroll
            for (int u = 0; u < 8; u++) {
                float4 k4 = *reinterpret_cast<const float4*>(&kt[pbase + u][d]);
                acc[u] = fmaf(x4.x, k4.x, acc[u]);
                acc[u] = fmaf(x4.y, k4.y, acc[u]);
                acc[u] = fmaf(x4.z, k4.z, acc[u]);
                acc[u] = fmaf(x4.w, k4.w, acc[u]);
            }
        }
        __syncthreads();
        if (c < 9) {
            #pragma unroll
            for (int i = 0; i < 4; i++) *reinterpret_cast<float4*>(&kt[kp[i]][kf[i]*4]) = kv[i];
            if (t < 128) *reinterpret_cast<float4*>(&xsc[xr][xf*4]) = xv;
        }
    }

    #pragma unroll
    for (int u = 0; u < 8; u++) {
        acc[u] += __shfl_xor_sync(0xffffffffu, acc[u], 8);
        acc[u] += __shfl_xor_sync(0xffffffffu, acc[u], 16);
    }
    if (q == 0) {
        #pragma unroll
        for (int u = 0; u < 8; u++) sims[r][pbase + u] = acc[u];
    }
    __syncthreads();

    // similarity output (coalesced)
    for (int l = t; l < 8 * POOL; l += 512) {
        int rr = l >> 7, pp = l & 127;
        out[OUT_SIM + (size_t)(rb + rr) * POOL + pp] = sims[rr][pp];
    }

    // top-4: warps 0..7 -> rows 0..7 (monotone-bits composite key,
    // smallest index on ties -> matches jax.lax.top_k)
    if (w < 8) {
        float vals[4];
        #pragma unroll
        for (int s = 0; s < 4; s++) vals[s] = sims[w][lane + 32*s];
        float vsum = 0.f;
        #pragma unroll
        for (int k = 0; k < TOPK; k++) {
            unsigned long long best = 0ull;
            #pragma unroll
            for (int s = 0; s < 4; s++) {
                unsigned u = __float_as_uint(vals[s]);
                u = (u & 0x80000000u) ? ~u : (u | 0x80000000u);
                unsigned long long comp =
                    ((unsigned long long)u << 32) | (127u - (lane + 32u*s));
                if (comp > best) best = comp;
            }
            #pragma unroll
            for (int o = 16; o; o >>= 1) {
                unsigned long long other = __shfl_xor_sync(0xffffffffu, best, o);
                if (other > best) best = other;
            }
            unsigned pool = 127u - (unsigned)(best & 0xffffffffu);
            unsigned ub = (unsigned)(best >> 32);
            unsigned orig = (ub & 0x80000000u) ? (ub ^ 0x80000000u) : ~ub;
            vsum += __uint_as_float(orig);
            if (lane == (int)(pool & 31u)) vals[pool >> 5] = -1e30f;
            if (lane == 0) g_idx[(rb + w) * TOPK + k] = (int)pool;
        }
        if (lane == 0) wsum[w] = vsum;
    }
    __syncthreads();

    if (t == 0) {
        float s = 0.f;
        #pragma unroll
        for (int i = 0; i < 8; i++) s += wsum[i];   // fixed order -> deterministic
        g_partial[blockIdx.x] = s;
    }
}

// ============================================================
// Kernel C: blocks 0..1023 -> gather (9 independent float4/thread,
// batch-load then batch-store). Block 1024 -> final reduce + usage.
// ============================================================
__global__ __launch_bounds__(256) void kC_gather_final(const float4* __restrict__ prompt,
                                                       float* __restrict__ out) {
    if (blockIdx.x < BATCH) {
        const int b = blockIdx.x;
        const int t = threadIdx.x;
        int idxs[TOPK];
        #pragma unroll
        for (int k = 0; k < TOPK; k++) idxs[k] = g_idx[b * TOPK + k];

        float4 vals[9];
        #pragma unroll
        for (int j = 0; j < 9; j++) {
            int pos = t + 256 * j;          // 0..2303 over [K=4][PD4=576]
            int k   = pos / PD4;
            int off = pos - k * PD4;
            vals[j] = prompt[(size_t)idxs[k] * PD4 + off];
        }
        float4* dst = reinterpret_cast<float4*>(out) + (size_t)b * (TOPK * PD4);
        #pragma unroll
        for (int j = 0; j < 9; j++) dst[t + 256 * j] = vals[j];
    } else {
        __shared__ float s[128];
        __shared__ int   histo[128];
        const int t = threadIdx.x;
        if (t < 128) { s[t] = g_partial[t]; histo[t] = 0; }
        __syncthreads();
        #pragma unroll
        for (int o = 64; o; o >>= 1) {
            if (t < o) s[t] += s[t + o];
            __syncthreads();
        }
        if (t == 0) out[OUT_RS] = s[0] * (1.0f / (float)BATCH);
        #pragma unroll
        for (int i = 0; i < 16; i++)
            atomicAdd(&histo[g_idx[t + 256 * i]], 1);
        __syncthreads();
        if (t < 128) out[OUT_US + t] = (float)histo[t];
    }
}

// ============================================================
extern "C" void kernel_launch(void* const* d_in, const int* in_sizes, int n_in,
                              void* d_out, int out_size) {
    const float* x      = (const float*)d_in[0];  // [1024, 100, 640]
    const float* prompt = (const float*)d_in[1];  // [128, 1, 2304]
    const float* pkey   = (const float*)d_in[2];  // [128, 640]
    float* out = (float*)d_out;

    k1_norm<<<BATCH + POOL, dim3(160, 2)>>>(
        reinterpret_cast<const float4*>(x),
        reinterpret_cast<const float4*>(pkey));
    kB_sim_topk<<<128, 512>>>(out);
    kC_gather_final<<<BATCH + 1, 256>>>(
        reinterpret_cast<const float4*>(prompt), out);
}

// round 5
// speedup vs baseline: 1.5940x; 1.0821x over previous
#include <cuda_runtime.h>
#include <cstdint>

// ---- problem constants ----
#define BATCH   1024
#define NNODES  100
#define KD      640      // key dim (5*128)
#define KD4     160      // key dim in float4
#define POOL    128
#define TOPK    4
#define PD      2304     // prompt dim
#define PD4     576

// ---- output layout (flat float32, reference return order) ----
#define OUT_RS  (BATCH*TOPK*PD)          // 9437184
#define OUT_SIM (OUT_RS + 1)             // 9437185
#define OUT_US  (OUT_SIM + BATCH*POOL)   // 9568257

// ---- device scratch ----
__device__ float g_xnorm[BATCH * KD];
__device__ float g_keynorm[POOL * KD];
__device__ int   g_idx[BATCH * TOPK];
__device__ float g_partial[128];

// ---- f32x2 packed-FMA helpers (sm_103a) ----
__device__ __forceinline__ void fma2(unsigned long long& acc,
                                     unsigned long long a,
                                     unsigned long long b) {
    asm("fma.rn.f32x2 %0, %1, %2, %0;" : "+l"(acc) : "l"(a), "l"(b));
}
__device__ __forceinline__ float unpack_sum(unsigned long long v) {
    float lo, hi;
    asm("mov.b64 {%0, %1}, %2;" : "=f"(lo), "=f"(hi) : "l"(v));
    return lo + hi;
}

// ============================================================
// Kernel 1: blocks 0..1023 -> per-row mean + L2 normalize
//           blocks 1024..1151 -> pool-key normalize
// Normalizing the SUM == normalizing the mean (scale invariance).
// ============================================================
__global__ __launch_bounds__(320, 4) void k1_norm(const float4* __restrict__ x,
                                                  const float4* __restrict__ pk) {
    const int c   = threadIdx.x;                        // 0..159
    const int tid = threadIdx.y * 160 + threadIdx.x;    // 0..319
    const int lane = tid & 31, warp = tid >> 5;

    __shared__ float4 part[160];
    __shared__ float  wss[10];

    if (blockIdx.x < BATCH) {
        const int row = blockIdx.x;
        const float4* xp = x + (size_t)row * (NNODES * KD4)
                             + (size_t)threadIdx.y * 50 * KD4 + c;
        float4 a = make_float4(0.f, 0.f, 0.f, 0.f);
        #pragma unroll 10
        for (int n = 0; n < 50; n++) {
            float4 v = xp[(size_t)n * KD4];
            a.x += v.x; a.y += v.y; a.z += v.z; a.w += v.w;
        }
        if (threadIdx.y == 1) part[c] = a;
        __syncthreads();
        float ss = 0.f;
        if (threadIdx.y == 0) {
            float4 b = part[c];
            a.x += b.x; a.y += b.y; a.z += b.z; a.w += b.w;
            ss = a.x*a.x + a.y*a.y + a.z*a.z + a.w*a.w;
        }
        #pragma unroll
        for (int o = 16; o; o >>= 1) ss += __shfl_xor_sync(0xffffffffu, ss, o);
        if (lane == 0) wss[warp] = ss;
        __syncthreads();
        if (threadIdx.y == 0) {
            float tot = wss[0] + wss[1] + wss[2] + wss[3] + wss[4];
            tot = fmaxf(tot, 1e-12f);
            float rs = rsqrtf(tot);
            rs = rs * (1.5f - 0.5f * tot * rs * rs);   // NR refine
            float4* o4 = reinterpret_cast<float4*>(g_xnorm);
            o4[(size_t)row * KD4 + c] = make_float4(a.x*rs, a.y*rs, a.z*rs, a.w*rs);
        }
    } else {
        const int p = blockIdx.x - BATCH;
        float4 v = make_float4(0.f, 0.f, 0.f, 0.f);
        float ss = 0.f;
        if (tid < 160) {
            v = pk[(size_t)p * KD4 + tid];
            ss = v.x*v.x + v.y*v.y + v.z*v.z + v.w*v.w;
        }
        #pragma unroll
        for (int o = 16; o; o >>= 1) ss += __shfl_xor_sync(0xffffffffu, ss, o);
        if (lane == 0) wss[warp] = ss;
        __syncthreads();
        float tot = wss[0] + wss[1] + wss[2] + wss[3] + wss[4];
        tot = fmaxf(tot, 1e-12f);
        float rs = rsqrtf(tot);
        rs = rs * (1.5f - 0.5f * tot * rs * rs);
        if (tid < 160) {
            float4* o4 = reinterpret_cast<float4*>(g_keynorm);
            o4[(size_t)p * KD4 + tid] = make_float4(v.x*rs, v.y*rs, v.z*rs, v.w*rs);
        }
    }
}

// ============================================================
// Kernel B: sim GEMM + top-4. 128 blocks x 512 threads.
// Thread (pg, ds): pg = t>>4 owns pools pg*4..+3; ds = t&15 owns
// dim-slot ds (one float4 per 64-dim chunk). Register tile:
// 8 rows x 4 pools of f32x2 accumulators. Keys via coalesced LDG
// (read once per block, L2-resident), x staged once in smem.
// No per-chunk barriers. fma.rn.f32x2 halves FFMA issue count.
// ============================================================
__global__ __launch_bounds__(512) void kB_sim_topk(float* __restrict__ out) {
    __shared__ float xs[8][644];       // 8 rows, padded (161 float4)
    __shared__ float sims[8][132];
    __shared__ float wsum[8];

    const int t = threadIdx.x;
    const int w = t >> 5, lane = t & 31;
    const int pg = t >> 4;             // 0..31 -> pools pg*4..pg*4+3
    const int ds = t & 15;             // dim slot within chunk
    const int rb = blockIdx.x * 8;

    // stage x rows (coalesced), one barrier
    {
        const float4* xg = reinterpret_cast<const float4*>(g_xnorm);
        #pragma unroll
        for (int i = 0; i < 3; i++) {
            int l = t + 512 * i;                // 0..1279 covers 1280
            if (l < 1280) {
                int r = l / 160, col = l - r * 160;
                *reinterpret_cast<float4*>(&xs[r][col * 4]) =
                    xg[(size_t)(rb + r) * KD4 + col];
            }
        }
    }
    __syncthreads();

    const ulonglong2* kg = reinterpret_cast<const ulonglong2*>(g_keynorm);

    unsigned long long acc[4][8];      // [pool u][row r]
    #pragma unroll
    for (int u = 0; u < 4; u++)
        #pragma unroll
        for (int r = 0; r < 8; r++) acc[u][r] = 0ull;

    #pragma unroll
    for (int c = 0; c < 10; c++) {
        // keys: 4 independent LDG.128 (coalesced across ds lanes)
        ulonglong2 kv[4];
        #pragma unroll
        for (int u = 0; u < 4; u++)
            kv[u] = kg[(size_t)(pg * 4 + u) * KD4 + c * 16 + ds];
        #pragma unroll
        for (int r = 0; r < 8; r++) {
            ulonglong2 xv = *reinterpret_cast<const ulonglong2*>(
                &xs[r][c * 64 + ds * 4]);
            #pragma unroll
            for (int u = 0; u < 4; u++) {
                fma2(acc[u][r], xv.x, kv[u].x);
                fma2(acc[u][r], xv.y, kv[u].y);
            }
        }
    }

    // reduce over the 16 ds lanes (low 4 lane bits)
    #pragma unroll
    for (int u = 0; u < 4; u++) {
        #pragma unroll
        for (int r = 0; r < 8; r++) {
            float v = unpack_sum(acc[u][r]);
            #pragma unroll
            for (int o = 8; o; o >>= 1) v += __shfl_xor_sync(0xffffffffu, v, o);
            if (ds == 0) sims[r][pg * 4 + u] = v;
        }
    }
    __syncthreads();

    // similarity output (coalesced)
    for (int l = t; l < 8 * POOL; l += 512) {
        int rr = l >> 7, pp = l & 127;
        out[OUT_SIM + (size_t)(rb + rr) * POOL + pp] = sims[rr][pp];
    }

    // top-4: warps 0..7 -> rows 0..7 (monotone-bits composite key,
    // smallest index on ties -> matches jax.lax.top_k)
    if (w < 8) {
        float vals[4];
        #pragma unroll
        for (int s = 0; s < 4; s++) vals[s] = sims[w][lane + 32*s];
        float vsum = 0.f;
        #pragma unroll
        for (int k = 0; k < TOPK; k++) {
            unsigned long long best = 0ull;
            #pragma unroll
            for (int s = 0; s < 4; s++) {
                unsigned u = __float_as_uint(vals[s]);
                u = (u & 0x80000000u) ? ~u : (u | 0x80000000u);
                unsigned long long comp =
                    ((unsigned long long)u << 32) | (127u - (lane + 32u*s));
                if (comp > best) best = comp;
            }
            #pragma unroll
            for (int o = 16; o; o >>= 1) {
                unsigned long long other = __shfl_xor_sync(0xffffffffu, best, o);
                if (other > best) best = other;
            }
            unsigned pool = 127u - (unsigned)(best & 0xffffffffu);
            unsigned ub = (unsigned)(best >> 32);
            unsigned orig = (ub & 0x80000000u) ? (ub ^ 0x80000000u) : ~ub;
            vsum += __uint_as_float(orig);
            if (lane == (int)(pool & 31u)) vals[pool >> 5] = -1e30f;
            if (lane == 0) g_idx[(rb + w) * TOPK + k] = (int)pool;
        }
        if (lane == 0) wsum[w] = vsum;
    }
    __syncthreads();

    if (t == 0) {
        float s = 0.f;
        #pragma unroll
        for (int i = 0; i < 8; i++) s += wsum[i];   // fixed order -> deterministic
        g_partial[blockIdx.x] = s;
    }
}

// ============================================================
// Kernel C: blocks 0..1023 -> gather (9 independent float4/thread,
// batch-load then batch-store). Block 1024 -> final reduce + usage.
// ============================================================
__global__ __launch_bounds__(256) void kC_gather_final(const float4* __restrict__ prompt,
                                                       float* __restrict__ out) {
    if (blockIdx.x < BATCH) {
        const int b = blockIdx.x;
        const int t = threadIdx.x;
        int idxs[TOPK];
        #pragma unroll
        for (int k = 0; k < TOPK; k++) idxs[k] = g_idx[b * TOPK + k];

        float4 vals[9];
        #pragma unroll
        for (int j = 0; j < 9; j++) {
            int pos = t + 256 * j;          // 0..2303 over [K=4][PD4=576]
            int k   = pos / PD4;
            int off = pos - k * PD4;
            vals[j] = prompt[(size_t)idxs[k] * PD4 + off];
        }
        float4* dst = reinterpret_cast<float4*>(out) + (size_t)b * (TOPK * PD4);
        #pragma unroll
        for (int j = 0; j < 9; j++) dst[t + 256 * j] = vals[j];
    } else {
        __shared__ float s[128];
        __shared__ int   histo[128];
        const int t = threadIdx.x;
        if (t < 128) { s[t] = g_partial[t]; histo[t] = 0; }
        __syncthreads();
        #pragma unroll
        for (int o = 64; o; o >>= 1) {
            if (t < o) s[t] += s[t + o];
            __syncthreads();
        }
        if (t == 0) out[OUT_RS] = s[0] * (1.0f / (float)BATCH);
        #pragma unroll
        for (int i = 0; i < 16; i++)
            atomicAdd(&histo[g_idx[t + 256 * i]], 1);
        __syncthreads();
        if (t < 128) out[OUT_US + t] = (float)histo[t];
    }
}

// ============================================================
extern "C" void kernel_launch(void* const* d_in, const int* in_sizes, int n_in,
                              void* d_out, int out_size) {
    const float* x      = (const float*)d_in[0];  // [1024, 100, 640]
    const float* prompt = (const float*)d_in[1];  // [128, 1, 2304]
    const float* pkey   = (const float*)d_in[2];  // [128, 640]
    float* out = (float*)d_out;

    k1_norm<<<BATCH + POOL, dim3(160, 2)>>>(
        reinterpret_cast<const float4*>(x),
        reinterpret_cast<const float4*>(pkey));
    kB_sim_topk<<<128, 512>>>(out);
    kC_gather_final<<<BATCH + 1, 256>>>(
        reinterpret_cast<const float4*>(prompt), out);
}